// round 2
// baseline (speedup 1.0000x reference)
#include <cuda_runtime.h>

#define N_NODES 50000
#define N_EDGES 800000
#define NODE_DIM 64
#define EDGE_DIM 32
#define HIDDEN 64

// Scratch (no cudaMalloc allowed): aggregation buffer + degree counts.
__device__ float g_agg[N_NODES * HIDDEN];
__device__ float g_deg[N_NODES];

// ---------------------------------------------------------------------------
// Kernel 0: zero the scratch buffers (graph-capturable, deterministic)
// ---------------------------------------------------------------------------
__global__ void zero_kernel() {
    int i = blockIdx.x * blockDim.x + threadIdx.x;
    int stride = gridDim.x * blockDim.x;
    for (int idx = i; idx < N_NODES * HIDDEN; idx += stride) g_agg[idx] = 0.0f;
    for (int idx = i; idx < N_NODES; idx += stride) g_deg[idx] = 0.0f;
}

// ---------------------------------------------------------------------------
// Kernel 1: per-edge message MLP + atomic scatter to g_agg.
// One warp computes 4 edges simultaneously; weights live in shared memory.
// Lane n holds hidden/output channels n and n+32.
//   x layout per edge (96 = 64 node + 32 edge):
//     x0 = node[src][lane], x1 = node[src][32+lane], x2 = edge[e][lane]
// ---------------------------------------------------------------------------
__global__ __launch_bounds__(256, 2)
void edge_kernel(const float* __restrict__ nf, const float* __restrict__ ef,
                 const float* __restrict__ w1, const float* __restrict__ b1,
                 const float* __restrict__ w2, const float* __restrict__ b2,
                 const int* __restrict__ src, const int* __restrict__ dst) {
    extern __shared__ float sh[];
    float* sW1 = sh;            // 2*96*64 = 12288
    float* sB1 = sh + 12288;    // 2*64   = 128
    float* sW2 = sh + 12416;    // 2*64*64= 8192
    float* sB2 = sh + 20608;    // 2*64   = 128  -> total 20736 floats

    for (int i = threadIdx.x; i < 12288; i += blockDim.x) sW1[i] = w1[i];
    for (int i = threadIdx.x; i < 8192;  i += blockDim.x) sW2[i] = w2[i];
    if (threadIdx.x < 128) sB1[threadIdx.x] = b1[threadIdx.x];
    else if (threadIdx.x < 256) sB2[threadIdx.x - 128] = b2[threadIdx.x - 128];
    __syncthreads();

    const int lane   = threadIdx.x & 31;
    const int warp   = (blockIdx.x * blockDim.x + threadIdx.x) >> 5;
    const int nwarps = (gridDim.x * blockDim.x) >> 5;

    for (int e0 = warp * 4; e0 < N_EDGES; e0 += nwarps * 4) {
        // ---- gather inputs (clamped for the remainder group) ----
        int   eidx[4];
        float x0[4], x1[4], x2[4];
        #pragma unroll
        for (int i = 0; i < 4; i++) {
            int e = e0 + i; if (e >= N_EDGES) e = N_EDGES - 1;
            eidx[i] = e;
            int s = src[e];
            x0[i] = nf[s * NODE_DIM + lane];
            x1[i] = nf[s * NODE_DIM + 32 + lane];
            x2[i] = ef[e * EDGE_DIM + lane];
        }

        // message accumulator, seeded with b2[0]+b2[1]
        float m0[4], m1[4];
        {
            float s0 = sB2[lane] + sB2[64 + lane];
            float s1 = sB2[32 + lane] + sB2[96 + lane];
            #pragma unroll
            for (int i = 0; i < 4; i++) { m0[i] = s0; m1[i] = s1; }
        }

        #pragma unroll
        for (int l = 0; l < 2; l++) {
            const float* W1 = sW1 + l * 6144;
            const float* W2 = sW2 + l * 4096;
            float h0[4], h1[4];
            {
                float bA = sB1[l * 64 + lane];
                float bB = sB1[l * 64 + 32 + lane];
                #pragma unroll
                for (int i = 0; i < 4; i++) { h0[i] = bA; h1[i] = bB; }
            }
            // h = x @ W1 : k runs over 96, split into 3 chunks of 32
            #pragma unroll
            for (int c = 0; c < 3; c++) {
                #pragma unroll 8
                for (int kk = 0; kk < 32; kk++) {
                    int k = c * 32 + kk;
                    float wA = W1[k * 64 + lane];
                    float wB = W1[k * 64 + 32 + lane];
                    #pragma unroll
                    for (int i = 0; i < 4; i++) {
                        float xi = (c == 0) ? x0[i] : ((c == 1) ? x1[i] : x2[i]);
                        float xk = __shfl_sync(0xFFFFFFFFu, xi, kk);
                        h0[i] = fmaf(xk, wA, h0[i]);
                        h1[i] = fmaf(xk, wB, h1[i]);
                    }
                }
            }
            #pragma unroll
            for (int i = 0; i < 4; i++) {
                h0[i] = fmaxf(h0[i], 0.0f);
                h1[i] = fmaxf(h1[i], 0.0f);
            }
            // m += h @ W2 : j runs over 64, 2 chunks of 32
            #pragma unroll
            for (int c = 0; c < 2; c++) {
                #pragma unroll 8
                for (int jj = 0; jj < 32; jj++) {
                    int j = c * 32 + jj;
                    float wA = W2[j * 64 + lane];
                    float wB = W2[j * 64 + 32 + lane];
                    #pragma unroll
                    for (int i = 0; i < 4; i++) {
                        float hi = (c == 0) ? h0[i] : h1[i];
                        float hj = __shfl_sync(0xFFFFFFFFu, hi, jj);
                        m0[i] = fmaf(hj, wA, m0[i]);
                        m1[i] = fmaf(hj, wB, m1[i]);
                    }
                }
            }
        }

        // ---- scatter to destination nodes ----
        #pragma unroll
        for (int i = 0; i < 4; i++) {
            if (e0 + i < N_EDGES) {
                int d = dst[eidx[i]];
                atomicAdd(&g_agg[d * HIDDEN + lane], m0[i]);
                atomicAdd(&g_agg[d * HIDDEN + 32 + lane], m1[i]);
                if (lane == 0) atomicAdd(&g_deg[d], 1.0f);
            }
        }
    }
}

// ---------------------------------------------------------------------------
// Kernel 2: node update MLP. One warp per node.
//   x (128) = [node(64), agg/deg (64)] -> 4 register chunks of 32.
// ---------------------------------------------------------------------------
__global__ __launch_bounds__(256)
void node_kernel(const float* __restrict__ nf,
                 const float* __restrict__ u1, const float* __restrict__ ub1,
                 const float* __restrict__ u2, const float* __restrict__ ub2,
                 float* __restrict__ out) {
    extern __shared__ float sh[];
    float* sW1 = sh;            // 128*64 = 8192
    float* sB1 = sh + 8192;     // 64
    float* sW2 = sh + 8256;     // 64*64 = 4096
    float* sB2 = sh + 12352;    // 64 -> total 12416 floats

    for (int i = threadIdx.x; i < 8192; i += blockDim.x) sW1[i] = u1[i];
    for (int i = threadIdx.x; i < 4096; i += blockDim.x) sW2[i] = u2[i];
    if (threadIdx.x < 64) sB1[threadIdx.x] = ub1[threadIdx.x];
    else if (threadIdx.x < 128) sB2[threadIdx.x - 64] = ub2[threadIdx.x - 64];
    __syncthreads();

    const int lane   = threadIdx.x & 31;
    const int warp   = (blockIdx.x * blockDim.x + threadIdx.x) >> 5;
    const int nwarps = (gridDim.x * blockDim.x) >> 5;

    for (int n = warp; n < N_NODES; n += nwarps) {
        float inv = 1.0f / (g_deg[n] + 1e-8f);
        float x0 = nf[n * NODE_DIM + lane];
        float x1 = nf[n * NODE_DIM + 32 + lane];
        float x2 = g_agg[n * HIDDEN + lane] * inv;
        float x3 = g_agg[n * HIDDEN + 32 + lane] * inv;

        float h0 = sB1[lane], h1 = sB1[32 + lane];
        #pragma unroll
        for (int c = 0; c < 4; c++) {
            #pragma unroll 8
            for (int kk = 0; kk < 32; kk++) {
                int k = c * 32 + kk;
                float xi = (c == 0) ? x0 : ((c == 1) ? x1 : ((c == 2) ? x2 : x3));
                float xk = __shfl_sync(0xFFFFFFFFu, xi, kk);
                h0 = fmaf(xk, sW1[k * 64 + lane], h0);
                h1 = fmaf(xk, sW1[k * 64 + 32 + lane], h1);
            }
        }
        h0 = fmaxf(h0, 0.0f); h1 = fmaxf(h1, 0.0f);

        float o0 = sB2[lane], o1 = sB2[32 + lane];
        #pragma unroll
        for (int c = 0; c < 2; c++) {
            #pragma unroll 8
            for (int jj = 0; jj < 32; jj++) {
                int j = c * 32 + jj;
                float hi = (c == 0) ? h0 : h1;
                float hj = __shfl_sync(0xFFFFFFFFu, hi, jj);
                o0 = fmaf(hj, sW2[j * 64 + lane], o0);
                o1 = fmaf(hj, sW2[j * 64 + 32 + lane], o1);
            }
        }
        out[n * NODE_DIM + lane] = o0;
        out[n * NODE_DIM + 32 + lane] = o1;
    }
}

// ---------------------------------------------------------------------------
extern "C" void kernel_launch(void* const* d_in, const int* in_sizes, int n_in,
                              void* d_out, int out_size) {
    const float* nf  = (const float*)d_in[0];   // node_features [50000,64]
    const float* ef  = (const float*)d_in[1];   // edge_features [800000,32]
    const float* mw1 = (const float*)d_in[2];   // msg_w1 [2,96,64]
    const float* mb1 = (const float*)d_in[3];   // msg_b1 [2,64]
    const float* mw2 = (const float*)d_in[4];   // msg_w2 [2,64,64]
    const float* mb2 = (const float*)d_in[5];   // msg_b2 [2,64]
    const float* uw1 = (const float*)d_in[6];   // upd_w1 [128,64]
    const float* ub1 = (const float*)d_in[7];   // upd_b1 [64]
    const float* uw2 = (const float*)d_in[8];   // upd_w2 [64,64]
    const float* ub2 = (const float*)d_in[9];   // upd_b2 [64]
    const int*   src = (const int*)d_in[10];    // [800000]
    const int*   dst = (const int*)d_in[11];    // [800000]
    float* out = (float*)d_out;                 // [50000,64]

    static_assert(sizeof(float) == 4, "");
    const int EDGE_SMEM = 20736 * 4;  // 82944 B
    const int NODE_SMEM = 12416 * 4;  // 49664 B
    cudaFuncSetAttribute(edge_kernel, cudaFuncAttributeMaxDynamicSharedMemorySize, EDGE_SMEM);
    cudaFuncSetAttribute(node_kernel, cudaFuncAttributeMaxDynamicSharedMemorySize, NODE_SMEM);

    zero_kernel<<<256, 256>>>();
    edge_kernel<<<296, 256, EDGE_SMEM>>>(nf, ef, mw1, mb1, mw2, mb2, src, dst);
    node_kernel<<<296, 256, NODE_SMEM>>>(nf, uw1, ub1, uw2, ub2, out);
}

// round 4
// speedup vs baseline: 2.5400x; 2.5400x over previous
#include <cuda_runtime.h>
#include <cuda_bf16.h>
#include <cstdint>

#define N_NODES 50000
#define N_EDGES 800000
#define NODE_DIM 64
#define EDGE_DIM 32
#define HIDDEN 64
#define NTILES 6250           // 800000 / 128 exactly

__device__ float g_agg[N_NODES * HIDDEN];
__device__ float g_deg[N_NODES];

// strides in bf16 halves (padded for bank-conflict-free ldmatrix / LDS)
#define XS  104
#define HS  72
#define W1S 104
#define W2S 72

// byte offsets in dynamic smem
#define OFF_XH  0u
#define OFF_XL  26624u
#define OFF_HH  53248u
#define OFF_HL  71680u
#define OFF_W1  90112u        // 4 * 64 * 104 * 2 = 53248
#define OFF_W2  143360u       // 4 * 64 * 72  * 2 = 36864
#define OFF_SRC 180224u
#define OFF_DST 180736u
#define OFF_B1  181248u       // 128 floats
#define OFF_B2  181760u       // 64 floats
#define SMEM_EDGE 182016

// ===================== helpers =====================
__device__ __forceinline__ uint32_t smem_u32(const void* p) {
    uint32_t a;
    asm("{ .reg .u64 t; cvta.to.shared.u64 t, %1; cvt.u32.u64 %0, t; }" : "=r"(a) : "l"(p));
    return a;
}
__device__ __forceinline__ uint32_t lds32(uint32_t a) {
    uint32_t v; asm volatile("ld.shared.b32 %0, [%1];" : "=r"(v) : "r"(a)); return v;
}
__device__ __forceinline__ void sts32(uint32_t a, uint32_t v) {
    asm volatile("st.shared.b32 [%0], %1;" :: "r"(a), "r"(v));
}
__device__ __forceinline__ void sts64(uint32_t a, uint32_t x, uint32_t y) {
    asm volatile("st.shared.v2.b32 [%0], {%1, %2};" :: "r"(a), "r"(x), "r"(y));
}
#define LDSM4(a, addr) \
    asm volatile("ldmatrix.sync.aligned.m8n8.x4.shared.b16 {%0,%1,%2,%3}, [%4];" \
        : "=r"((a)[0]), "=r"((a)[1]), "=r"((a)[2]), "=r"((a)[3]) : "r"(addr))

#define MMA(d, a, b0, b1) \
    asm volatile("mma.sync.aligned.m16n8k16.row.col.f32.bf16.bf16.f32 " \
        "{%0,%1,%2,%3}, {%4,%5,%6,%7}, {%8,%9}, {%0,%1,%2,%3};" \
        : "+f"((d)[0]), "+f"((d)[1]), "+f"((d)[2]), "+f"((d)[3]) \
        : "r"((a)[0]), "r"((a)[1]), "r"((a)[2]), "r"((a)[3]), "r"(b0), "r"(b1))

__device__ __forceinline__ uint32_t bits_bf2(__nv_bfloat162 v) { return *(uint32_t*)&v; }

// ===================== zero scratch =====================
__global__ void zero_kernel() {
    int i = blockIdx.x * blockDim.x + threadIdx.x, s = gridDim.x * blockDim.x;
    for (int x = i; x < N_NODES * HIDDEN; x += s) g_agg[x] = 0.0f;
    for (int x = i; x < N_NODES; x += s) g_deg[x] = 0.0f;
}

// ===================== edge kernel (mma.sync bf16 hi/lo) =====================
__global__ __launch_bounds__(256, 1)
void edge_mma_kernel(const float* __restrict__ nf, const float* __restrict__ ef,
                     const float* __restrict__ w1, const float* __restrict__ b1,
                     const float* __restrict__ w2, const float* __restrict__ b2,
                     const int* __restrict__ src, const int* __restrict__ dst) {
    extern __shared__ char smem[];
    const uint32_t sb = smem_u32(smem);
    const int tid = threadIdx.x, warp = tid >> 5, lane = tid & 31;

    // ---- stage weights transposed [n][k], bf16 hi/lo, padded strides ----
    for (int idx = tid; idx < 2 * 96 * 64; idx += 256) {
        int l = idx / 6144, rem = idx % 6144, k = rem / 64, n = rem % 64;
        float wv = w1[idx];
        __nv_bfloat16 hi = __float2bfloat16(wv);
        __nv_bfloat16 lo = __float2bfloat16(wv - __bfloat162float(hi));
        *(__nv_bfloat16*)(smem + OFF_W1 + (((l * 2 + 0) * 64 + n) * W1S + k) * 2) = hi;
        *(__nv_bfloat16*)(smem + OFF_W1 + (((l * 2 + 1) * 64 + n) * W1S + k) * 2) = lo;
    }
    for (int idx = tid; idx < 2 * 64 * 64; idx += 256) {
        int l = idx / 4096, rem = idx % 4096, k = rem / 64, n = rem % 64;
        float wv = w2[idx];
        __nv_bfloat16 hi = __float2bfloat16(wv);
        __nv_bfloat16 lo = __float2bfloat16(wv - __bfloat162float(hi));
        *(__nv_bfloat16*)(smem + OFF_W2 + (((l * 2 + 0) * 64 + n) * W2S + k) * 2) = hi;
        *(__nv_bfloat16*)(smem + OFF_W2 + (((l * 2 + 1) * 64 + n) * W2S + k) * 2) = lo;
    }
    float* sB1 = (float*)(smem + OFF_B1);
    float* sB2 = (float*)(smem + OFF_B2);
    if (tid < 128) sB1[tid] = b1[tid];
    if (tid >= 128 && tid < 192) sB2[tid - 128] = b2[tid - 128] + b2[tid - 64];
    int* sS = (int*)(smem + OFF_SRC);
    int* sD = (int*)(smem + OFF_DST);

    const int m0 = warp * 16;
    const int g = lane >> 2, j4 = lane & 3;
    // ldmatrix lane addresses (A tile at (m0, kt*16): add kt*32 bytes)
    const uint32_t arow = (uint32_t)(lane & 15);
    const uint32_t acol = (lane & 16) ? 8u : 0u;
    const uint32_t xh_lane = sb + OFF_XH + ((m0 + arow) * XS + acol) * 2;
    const uint32_t xl_lane = sb + OFF_XL + ((m0 + arow) * XS + acol) * 2;
    const uint32_t hh_lane = sb + OFF_HH + ((m0 + arow) * HS + acol) * 2;
    const uint32_t hl_lane = sb + OFF_HL + ((m0 + arow) * HS + acol) * 2;
    // B-fragment lane base offsets
    const uint32_t w1_lane = sb + OFF_W1 + (uint32_t)(g * W1S + j4 * 2) * 2;
    const uint32_t w2_lane = sb + OFF_W2 + (uint32_t)(g * W2S + j4 * 2) * 2;

    for (int tile = blockIdx.x; tile < NTILES; tile += (int)gridDim.x) {
        const int base = tile * 128;
        __syncthreads();   // previous tile fully consumed (X, sS, sD)
        if (tid < 128) { sS[tid] = src[base + tid]; sD[tid] = dst[base + tid]; }
        __syncthreads();

        // ---- gather X (128 x 96 f32) -> bf16 hi/lo padded smem ----
        for (int v = tid; v < 3072; v += 256) {
            int r = v / 24, k0 = (v % 24) * 4;
            float4 x4 = (k0 < 64)
                ? *(const float4*)(nf + (size_t)sS[r] * NODE_DIM + k0)
                : *(const float4*)(ef + (size_t)(base + r) * EDGE_DIM + (k0 - 64));
            __nv_bfloat162 hA = __floats2bfloat162_rn(x4.x, x4.y);
            __nv_bfloat162 hB = __floats2bfloat162_rn(x4.z, x4.w);
            float2 fA = __bfloat1622float2(hA), fB = __bfloat1622float2(hB);
            __nv_bfloat162 lA = __floats2bfloat162_rn(x4.x - fA.x, x4.y - fA.y);
            __nv_bfloat162 lB = __floats2bfloat162_rn(x4.z - fB.x, x4.w - fB.y);
            uint32_t off = (uint32_t)(r * XS + k0) * 2;
            sts64(sb + OFF_XH + off, bits_bf2(hA), bits_bf2(hB));
            sts64(sb + OFF_XL + off, bits_bf2(lA), bits_bf2(lB));
        }
        __syncthreads();

        float d2[8][4];
        #pragma unroll
        for (int t = 0; t < 8; t++) { d2[t][0] = d2[t][1] = d2[t][2] = d2[t][3] = 0.0f; }

        #pragma unroll
        for (int l = 0; l < 2; l++) {
            float d1[8][4];
            #pragma unroll
            for (int t = 0; t < 8; t++) { d1[t][0] = d1[t][1] = d1[t][2] = d1[t][3] = 0.0f; }

            // ---- layer 1: D1 = X @ W1[l], K=96 ----
            #pragma unroll
            for (int kt = 0; kt < 6; kt++) {
                uint32_t ah[4], al[4];
                LDSM4(ah, xh_lane + kt * 32);
                LDSM4(al, xl_lane + kt * 32);
                #pragma unroll
                for (int nt = 0; nt < 8; nt++) {
                    uint32_t wb  = w1_lane + (uint32_t)((l * 2 * 64 + nt * 8) * W1S) * 2 + kt * 32;
                    uint32_t wbl = wb + (uint32_t)(64 * W1S) * 2;
                    uint32_t bh0 = lds32(wb),  bh1 = lds32(wb + 16);
                    uint32_t bl0 = lds32(wbl), bl1 = lds32(wbl + 16);
                    MMA(d1[nt], ah, bh0, bh1);
                    MMA(d1[nt], ah, bl0, bl1);
                    MMA(d1[nt], al, bh0, bh1);
                }
            }

            // ---- epilogue 1: +b1, relu, split -> H (warp-private rows) ----
            __syncwarp();
            #pragma unroll
            for (int nt = 0; nt < 8; nt++) {
                int c0 = nt * 8 + j4 * 2;
                float bA = sB1[l * 64 + c0], bB = sB1[l * 64 + c0 + 1];
                float h0 = fmaxf(d1[nt][0] + bA, 0.0f);
                float h1 = fmaxf(d1[nt][1] + bB, 0.0f);
                float h2 = fmaxf(d1[nt][2] + bA, 0.0f);
                float h3 = fmaxf(d1[nt][3] + bB, 0.0f);
                __nv_bfloat162 hiA = __floats2bfloat162_rn(h0, h1);
                float2 fA = __bfloat1622float2(hiA);
                __nv_bfloat162 loA = __floats2bfloat162_rn(h0 - fA.x, h1 - fA.y);
                __nv_bfloat162 hiB = __floats2bfloat162_rn(h2, h3);
                float2 fB = __bfloat1622float2(hiB);
                __nv_bfloat162 loB = __floats2bfloat162_rn(h2 - fB.x, h3 - fB.y);
                uint32_t offA = (uint32_t)((m0 + g) * HS + c0) * 2;
                uint32_t offB = (uint32_t)((m0 + g + 8) * HS + c0) * 2;
                sts32(sb + OFF_HH + offA, bits_bf2(hiA));
                sts32(sb + OFF_HL + offA, bits_bf2(loA));
                sts32(sb + OFF_HH + offB, bits_bf2(hiB));
                sts32(sb + OFF_HL + offB, bits_bf2(loB));
            }
            __syncwarp();

            // ---- layer 2: D2 += H @ W2[l], K=64 ----
            #pragma unroll
            for (int kt = 0; kt < 4; kt++) {
                uint32_t ah[4], al[4];
                LDSM4(ah, hh_lane + kt * 32);
                LDSM4(al, hl_lane + kt * 32);
                #pragma unroll
                for (int nt = 0; nt < 8; nt++) {
                    uint32_t wb  = w2_lane + (uint32_t)((l * 2 * 64 + nt * 8) * W2S) * 2 + kt * 32;
                    uint32_t wbl = wb + (uint32_t)(64 * W2S) * 2;
                    uint32_t bh0 = lds32(wb),  bh1 = lds32(wb + 16);
                    uint32_t bl0 = lds32(wbl), bl1 = lds32(wbl + 16);
                    MMA(d2[nt], ah, bh0, bh1);
                    MMA(d2[nt], ah, bl0, bl1);
                    MMA(d2[nt], al, bh0, bh1);
                }
            }
        }

        // ---- epilogue 2: +sum(b2), pair-shuffle to quads, v4 red scatter ----
        #pragma unroll
        for (int nt = 0; nt < 8; nt++) {
            int c0 = nt * 8 + j4 * 2;
            float v0 = d2[nt][0] + sB2[c0];
            float v1 = d2[nt][1] + sB2[c0 + 1];
            float v2 = d2[nt][2] + sB2[c0];
            float v3 = d2[nt][3] + sB2[c0 + 1];
            float e0 = __shfl_xor_sync(0xFFFFFFFFu, v0, 1);
            float e1 = __shfl_xor_sync(0xFFFFFFFFu, v1, 1);
            float e2 = __shfl_xor_sync(0xFFFFFFFFu, v2, 1);
            float e3 = __shfl_xor_sync(0xFFFFFFFFu, v3, 1);
            int colbase = nt * 8 + ((lane >> 1) & 1) * 4;
            int r; float q0, q1, q2, q3;
            if (lane & 1) { r = m0 + g + 8; q0 = e2; q1 = e3; q2 = v2; q3 = v3; }
            else          { r = m0 + g;     q0 = v0; q1 = v1; q2 = e0; q3 = e1; }
            float* gp = g_agg + (size_t)sD[r] * HIDDEN + colbase;
            asm volatile("red.global.add.v4.f32 [%0], {%1, %2, %3, %4};"
                         :: "l"(gp), "f"(q0), "f"(q1), "f"(q2), "f"(q3) : "memory");
            if (nt == 0 && (((lane >> 1) & 1) == 0))
                atomicAdd(&g_deg[sD[r]], 1.0f);
        }
    }
}

// ===================== node kernel (SIMT, 4 nodes/warp) =====================
__global__ __launch_bounds__(256)
void node_kernel(const float* __restrict__ nf,
                 const float* __restrict__ u1, const float* __restrict__ ub1,
                 const float* __restrict__ u2, const float* __restrict__ ub2,
                 float* __restrict__ out) {
    extern __shared__ float sh[];
    float* sW1 = sh;          // 128*64
    float* sB1 = sh + 8192;   // 64
    float* sW2 = sh + 8256;   // 64*64
    float* sB2 = sh + 12352;  // 64
    for (int i = threadIdx.x; i < 8192; i += blockDim.x) sW1[i] = u1[i];
    for (int i = threadIdx.x; i < 4096; i += blockDim.x) sW2[i] = u2[i];
    if (threadIdx.x < 64) sB1[threadIdx.x] = ub1[threadIdx.x];
    else if (threadIdx.x < 128) sB2[threadIdx.x - 64] = ub2[threadIdx.x - 64];
    __syncthreads();

    const int lane = threadIdx.x & 31;
    const int warp = (blockIdx.x * blockDim.x + threadIdx.x) >> 5;
    const int nwarps = (gridDim.x * blockDim.x) >> 5;

    for (int n0 = warp * 4; n0 < N_NODES; n0 += nwarps * 4) {
        float x0[4], x1[4], x2[4], x3[4];
        #pragma unroll
        for (int i = 0; i < 4; i++) {
            int n = n0 + i; if (n >= N_NODES) n = N_NODES - 1;
            float inv = 1.0f / (g_deg[n] + 1e-8f);
            x0[i] = nf[n * NODE_DIM + lane];
            x1[i] = nf[n * NODE_DIM + 32 + lane];
            x2[i] = g_agg[n * HIDDEN + lane] * inv;
            x3[i] = g_agg[n * HIDDEN + 32 + lane] * inv;
        }
        float h0[4], h1[4];
        #pragma unroll
        for (int i = 0; i < 4; i++) { h0[i] = sB1[lane]; h1[i] = sB1[32 + lane]; }
        #pragma unroll
        for (int c = 0; c < 4; c++) {
            #pragma unroll 8
            for (int kk = 0; kk < 32; kk++) {
                int k = c * 32 + kk;
                float wA = sW1[k * 64 + lane], wB = sW1[k * 64 + 32 + lane];
                #pragma unroll
                for (int i = 0; i < 4; i++) {
                    float xi = (c == 0) ? x0[i] : ((c == 1) ? x1[i] : ((c == 2) ? x2[i] : x3[i]));
                    float xk = __shfl_sync(0xFFFFFFFFu, xi, kk);
                    h0[i] = fmaf(xk, wA, h0[i]);
                    h1[i] = fmaf(xk, wB, h1[i]);
                }
            }
        }
        #pragma unroll
        for (int i = 0; i < 4; i++) { h0[i] = fmaxf(h0[i], 0.0f); h1[i] = fmaxf(h1[i], 0.0f); }
        float o0[4], o1[4];
        #pragma unroll
        for (int i = 0; i < 4; i++) { o0[i] = sB2[lane]; o1[i] = sB2[32 + lane]; }
        #pragma unroll
        for (int c = 0; c < 2; c++) {
            #pragma unroll 8
            for (int jj = 0; jj < 32; jj++) {
                int j = c * 32 + jj;
                float wA = sW2[j * 64 + lane], wB = sW2[j * 64 + 32 + lane];
                #pragma unroll
                for (int i = 0; i < 4; i++) {
                    float hi = (c == 0) ? h0[i] : h1[i];
                    float hj = __shfl_sync(0xFFFFFFFFu, hi, jj);
                    o0[i] = fmaf(hj, wA, o0[i]);
                    o1[i] = fmaf(hj, wB, o1[i]);
                }
            }
        }
        #pragma unroll
        for (int i = 0; i < 4; i++) {
            int n = n0 + i;
            if (n < N_NODES) {
                out[n * NODE_DIM + lane] = o0[i];
                out[n * NODE_DIM + 32 + lane] = o1[i];
            }
        }
    }
}

// ===================== launch =====================
extern "C" void kernel_launch(void* const* d_in, const int* in_sizes, int n_in,
                              void* d_out, int out_size) {
    const float* nf  = (const float*)d_in[0];
    const float* ef  = (const float*)d_in[1];
    const float* mw1 = (const float*)d_in[2];
    const float* mb1 = (const float*)d_in[3];
    const float* mw2 = (const float*)d_in[4];
    const float* mb2 = (const float*)d_in[5];
    const float* uw1 = (const float*)d_in[6];
    const float* ub1 = (const float*)d_in[7];
    const float* uw2 = (const float*)d_in[8];
    const float* ub2 = (const float*)d_in[9];
    const int*   src = (const int*)d_in[10];
    const int*   dst = (const int*)d_in[11];
    float* out = (float*)d_out;

    const int NODE_SMEM = 12416 * 4;
    cudaFuncSetAttribute(edge_mma_kernel, cudaFuncAttributeMaxDynamicSharedMemorySize, SMEM_EDGE);
    cudaFuncSetAttribute(node_kernel, cudaFuncAttributeMaxDynamicSharedMemorySize, NODE_SMEM);

    zero_kernel<<<256, 256>>>();
    edge_mma_kernel<<<148, 256, SMEM_EDGE>>>(nf, ef, mw1, mb1, mw2, mb2, src, dst);
    node_kernel<<<200, 256, NODE_SMEM>>>(nf, uw1, ub1, uw2, ub2, out);
}